// round 15
// baseline (speedup 1.0000x reference)
#include <cuda_runtime.h>
#include <cuda_fp16.h>
#include <cstdint>

// ---------------- problem constants ----------------
#define N_ROWS   16384
#define N_CODES  8192
#define DIM      512
#define Q_ELEMS  (N_ROWS * DIM)

// ---------------- GEMM tiling (fp16 in, fp16 accum) ----------------
#define BM 128
#define BN 128
#define KC 64                 // K elems per stage = 128 B per row
#define NSTAGES (DIM / KC)    // 8
#define CH 8                  // codes per argmin chunk
#define NCH (N_CODES / CH)    // 1024 chunk-mins per row
#define EPS 4.0e-4f
#define MAXCAND 64            // max candidate chunks per row

// dynamic smem: 2 stages x (A 16KB + B 16KB) = 65536; enorm after -> 3 CTAs/SM
#define STG_BYTES 32768
#define SM_BOFF   16384
#define SM_ENORM  65536
#define SM_TOTAL  (65536 + 512)

#define NPART 64              // scalar reduction partials

// ---------------- scratch (device globals; no allocation allowed) ----------------
__device__ __align__(256) __half g_hx[(size_t)N_ROWS * DIM];
__device__ __align__(256) __half g_he[(size_t)N_CODES * DIM];
__device__ float  g_xnorm[N_ROWS];
__device__ float  g_enorm[N_CODES];
__device__ __align__(16) __half g_cmin[(size_t)N_ROWS * NCH];   // d~ chunk mins, fp16
__device__ float  g_rowsq[N_ROWS];
__device__ float  g_part[NPART];
__device__ int    g_maxidx;

// ---------------- PTX helpers ----------------
__device__ __forceinline__ uint32_t smem_u32(const void* p) {
    uint32_t a;
    asm("{ .reg .u64 t; cvta.to.shared.u64 t, %1; cvt.u32.u64 %0, t; }"
        : "=r"(a) : "l"(p));
    return a;
}
__device__ __forceinline__ void cp16(uint32_t dst, const void* src) {
    asm volatile("cp.async.cg.shared.global [%0], [%1], 16;" :: "r"(dst), "l"(src) : "memory");
}
__device__ __forceinline__ void cp4(uint32_t dst, const void* src) {
    asm volatile("cp.async.ca.shared.global [%0], [%1], 4;" :: "r"(dst), "l"(src) : "memory");
}
#define CP_COMMIT() asm volatile("cp.async.commit_group;" ::: "memory")
#define CP_WAIT(n)  asm volatile("cp.async.wait_group %0;" :: "n"(n) : "memory")

#define SWZ(b) ((b) ^ (((b) >> 3) & 0x70))

__device__ __forceinline__ void ldsm4(uint32_t* r, uint32_t addr) {
    asm volatile("ldmatrix.sync.aligned.m8n8.x4.shared.b16 {%0,%1,%2,%3}, [%4];"
                 : "=r"(r[0]), "=r"(r[1]), "=r"(r[2]), "=r"(r[3]) : "r"(addr));
}
// fp16 in, fp16 accum: C/D are 2 b32 regs (4 halves)
__device__ __forceinline__ void mma16816_h(uint32_t* c, const uint32_t* a, const uint32_t* b) {
    asm volatile(
        "mma.sync.aligned.m16n8k16.row.col.f16.f16.f16.f16 "
        "{%0,%1}, {%2,%3,%4,%5}, {%6,%7}, {%0,%1};"
        : "+r"(c[0]), "+r"(c[1])
        : "r"(a[0]), "r"(a[1]), "r"(a[2]), "r"(a[3]), "r"(b[0]), "r"(b[1]));
}

// ---------------- kernels ----------------

// one warp per row: fp32 norm + fp16 convert (block 0 also resets g_maxidx)
__global__ void convert_kernel(const float* __restrict__ x, const float* __restrict__ emb) {
    if (blockIdx.x == 0 && threadIdx.x == 0) g_maxidx = 0;
    int warp = (blockIdx.x * blockDim.x + threadIdx.x) >> 5;
    int lane = threadIdx.x & 31;
    const float* src; __half* dst; float* nrm; int row;
    if (warp < N_ROWS) { src = x; dst = g_hx; nrm = g_xnorm; row = warp; }
    else               { src = emb; dst = g_he; nrm = g_enorm; row = warp - N_ROWS; }
    const float4* p = reinterpret_cast<const float4*>(src + (size_t)row * DIM);
    uint2* o = reinterpret_cast<uint2*>(dst + (size_t)row * DIM);
    float s = 0.f;
    #pragma unroll
    for (int c = lane; c < DIM / 4; c += 32) {
        float4 v = p[c];
        s += v.x * v.x + v.y * v.y + v.z * v.z + v.w * v.w;
        __half2 lo = __floats2half2_rn(v.x, v.y);
        __half2 hi = __floats2half2_rn(v.z, v.w);
        uint2 u;
        u.x = *reinterpret_cast<unsigned*>(&lo);
        u.y = *reinterpret_cast<unsigned*>(&hi);
        o[c] = u;
    }
    #pragma unroll
    for (int off = 16; off; off >>= 1) s += __shfl_xor_sync(0xffffffffu, s, off);
    if (lane == 0) nrm[row] = s;
}

// fp16 HMMA GEMM: 128x128xK512 per CTA, 256 thr, 2-stage cp.async, 3 CTAs/SM.
// Epilogue: d~ = enorm - 2*dot, per-row min over 8-code chunks -> g_cmin (fp16).
__global__ void __launch_bounds__(256, 3) vq_gemm_kernel() {
    extern __shared__ __align__(1024) char smem[];
    const int tid = threadIdx.x;
    const int w = tid >> 5, l = tid & 31;
    const int rowBase = blockIdx.x * BM;
    const int cb = blockIdx.y * BN;
    const uint32_t sb = smem_u32(smem);
    float* senorm = reinterpret_cast<float*>(smem + SM_ENORM);

    // enorm tile via cp.async, joins stage-0 commit group (needed only in epilogue)
    if (tid < BN) cp4(sb + SM_ENORM + tid * 4u, g_enorm + cb + tid);

    // warp layout: 2 (M) x 4 (N); warp tile 64 x 32
    const int m0 = (w >> 2) * 64;
    const int n0 = (w & 3) * 32;
    const int aRowLane = l & 15;
    const int aChunkHi = l >> 4;
    const int bRowLane = ((l >> 4) & 1) * 8 + (l & 7);
    const int bChunkHi = (l >> 3) & 1;

    uint32_t c[4][4][2];
    #pragma unroll
    for (int mt = 0; mt < 4; mt++)
        #pragma unroll
        for (int nt = 0; nt < 4; nt++) { c[mt][nt][0] = 0u; c[mt][nt][1] = 0u; }

    auto load_stage = [&](int kc, int s) {
        const int kb = kc * KC;
        const uint32_t stg = sb + (uint32_t)s * STG_BYTES;
        #pragma unroll
        for (int q = 0; q < 4; q++) {
            int t = tid + q * 256;
            int r = t >> 3, ch = t & 7;
            cp16(stg + SWZ((uint32_t)(r * 128 + ch * 16)),
                 g_hx + (size_t)(rowBase + r) * DIM + kb + ch * 8);
        }
        #pragma unroll
        for (int q = 0; q < 4; q++) {
            int t = tid + q * 256;
            int r = t >> 3, ch = t & 7;
            cp16(stg + SM_BOFF + SWZ((uint32_t)(r * 128 + ch * 16)),
                 g_he + (size_t)(cb + r) * DIM + kb + ch * 8);
        }
        CP_COMMIT();
    };

    load_stage(0, 0);
    load_stage(1, 1);

    #pragma unroll
    for (int i = 0; i < NSTAGES; i++) {
        if (i < NSTAGES - 1) CP_WAIT(1); else CP_WAIT(0);
        __syncthreads();
        const uint32_t aStg = sb + (uint32_t)(i & 1) * STG_BYTES;
        const uint32_t bStg = aStg + SM_BOFF;
        #pragma unroll
        for (int ks = 0; ks < 4; ks++) {
            uint32_t a[4][4], b[4][2];
            #pragma unroll
            for (int mt = 0; mt < 4; mt++) {
                uint32_t off = (uint32_t)((m0 + mt * 16 + aRowLane) * 128
                                          + (ks * 2 + aChunkHi) * 16);
                ldsm4(a[mt], aStg + SWZ(off));
            }
            #pragma unroll
            for (int nt2 = 0; nt2 < 2; nt2++) {
                uint32_t r4[4];
                uint32_t off = (uint32_t)((n0 + nt2 * 16 + bRowLane) * 128
                                          + (ks * 2 + bChunkHi) * 16);
                ldsm4(r4, bStg + SWZ(off));
                b[nt2 * 2][0] = r4[0]; b[nt2 * 2][1] = r4[1];
                b[nt2 * 2 + 1][0] = r4[2]; b[nt2 * 2 + 1][1] = r4[3];
            }
            #pragma unroll
            for (int mt = 0; mt < 4; mt++)
                #pragma unroll
                for (int nt = 0; nt < 4; nt++)
                    mma16816_h(c[mt][nt], a[mt], b[nt]);
        }
        __syncthreads();                            // readers done with buf (i&1)
        if (i + 2 < NSTAGES) load_stage(i + 2, i & 1);
        else CP_COMMIT();                           // keep wait-depth invariant at drain
    }

    // ---- epilogue: chunk (8-code) mins -> smem staging -> coalesced fp16 gmem
    __syncthreads();
    float* sbuf = reinterpret_cast<float*>(smem);   // [128][20] = 10240 B, fits stage 0

    #pragma unroll
    for (int mt = 0; mt < 4; mt++) {
        #pragma unroll
        for (int nt = 0; nt < 4; nt++) {
            const int colBase = n0 + nt * 8 + (l & 3) * 2;
            float en0 = senorm[colBase], en1 = senorm[colBase + 1];
            __half2 h0 = *reinterpret_cast<__half2*>(&c[mt][nt][0]);  // row r
            __half2 h1 = *reinterpret_cast<__half2*>(&c[mt][nt][1]);  // row r+8
            float v0 = fminf(en0 - 2.0f * __low2float(h0), en1 - 2.0f * __high2float(h0));
            float v1 = fminf(en0 - 2.0f * __low2float(h1), en1 - 2.0f * __high2float(h1));
            #pragma unroll
            for (int off = 1; off <= 2; off <<= 1) {
                v0 = fminf(v0, __shfl_xor_sync(0xffffffffu, v0, off));
                v1 = fminf(v1, __shfl_xor_sync(0xffffffffu, v1, off));
            }
            if ((l & 3) == 0) {
                int rloc = m0 + mt * 16 + (l >> 2);
                int chLoc = (w & 3) * 4 + nt;
                sbuf[rloc * 20 + chLoc] = v0;
                sbuf[(rloc + 8) * 20 + chLoc] = v1;
            }
        }
    }
    __syncthreads();
    {
        int row = tid >> 1, half = tid & 1;
        const float* s = &sbuf[row * 20 + half * 8];
        __half2 p0 = __floats2half2_rn(s[0], s[1]);
        __half2 p1 = __floats2half2_rn(s[2], s[3]);
        __half2 p2 = __floats2half2_rn(s[4], s[5]);
        __half2 p3 = __floats2half2_rn(s[6], s[7]);
        uint4 o;
        o.x = *reinterpret_cast<unsigned*>(&p0);
        o.y = *reinterpret_cast<unsigned*>(&p1);
        o.z = *reinterpret_cast<unsigned*>(&p2);
        o.w = *reinterpret_cast<unsigned*>(&p3);
        __half* dst = &g_cmin[(size_t)(blockIdx.x * BM + row) * NCH + blockIdx.y * 16 + half * 8];
        *reinterpret_cast<uint4*>(dst) = o;
    }
}

// block-per-row fused select, 64 threads (2 warps) for row concurrency.
// x-row prefetched via cp.async during the cmin scan; per-warp register-held
// best keys (packed u64 = exact first-index ties); fused gather/ST/rowsq.
__global__ void __launch_bounds__(64) select_kernel(const float* __restrict__ x,
                                                    const float* __restrict__ emb,
                                                    float* __restrict__ out) {
    __shared__ __align__(16) float sx[DIM];
    __shared__ float sred[2];
    __shared__ int   slist[MAXCAND];
    __shared__ int   scount;
    __shared__ unsigned long long swkey[2];
    __shared__ int   sbesti;

    const int row = blockIdx.x;
    const int tid = threadIdx.x, w = tid >> 5, l = tid & 31;
    const uint32_t sxb = smem_u32(sx);

    // prefetch x row: 2 x 16B per thread (overlaps with cmin scan below)
    cp16(sxb + tid * 16u, x + (size_t)row * DIM + tid * 4);
    cp16(sxb + (tid + 64) * 16u, x + (size_t)row * DIM + (tid + 64) * 4);
    CP_COMMIT();
    if (tid == 0) scount = 0;

    // scan: each thread holds 16 chunk-mins (2 x uint4), coalesced 2KB row
    const uint4* cm = reinterpret_cast<const uint4*>(&g_cmin[(size_t)row * NCH]);
    float fv[2][8];
    float lmin = 3.4028235e38f;
    #pragma unroll
    for (int p = 0; p < 2; p++) {
        uint4 u = cm[tid + p * 64];
        float2 f0 = __half22float2(*reinterpret_cast<__half2*>(&u.x));
        float2 f1 = __half22float2(*reinterpret_cast<__half2*>(&u.y));
        float2 f2 = __half22float2(*reinterpret_cast<__half2*>(&u.z));
        float2 f3 = __half22float2(*reinterpret_cast<__half2*>(&u.w));
        fv[p][0] = f0.x; fv[p][1] = f0.y; fv[p][2] = f1.x; fv[p][3] = f1.y;
        fv[p][4] = f2.x; fv[p][5] = f2.y; fv[p][6] = f3.x; fv[p][7] = f3.y;
        #pragma unroll
        for (int e = 0; e < 8; e++) lmin = fminf(lmin, fv[p][e]);
    }
    #pragma unroll
    for (int off = 16; off; off >>= 1) lmin = fminf(lmin, __shfl_xor_sync(0xffffffffu, lmin, off));
    if (l == 0) sred[w] = lmin;
    __syncthreads();
    const float thr = fminf(sred[0], sred[1]) + EPS;

    #pragma unroll
    for (int p = 0; p < 2; p++)
        #pragma unroll
        for (int e = 0; e < 8; e++) {
            if (fv[p][e] <= thr) {
                int q = atomicAdd(&scount, 1);
                if (q < MAXCAND) slist[q] = (tid + p * 64) * 8 + e;  // unordered OK (key-min)
            }
        }
    CP_WAIT(0);                 // x row resident in sx
    __syncthreads();
    const int count = min(scount, MAXCAND);
    const int ncodes = count * CH;
    const float xn = g_xnorm[row];

    // flat-parallel exact fp32 rescore: warp w handles codes w, w+2, ...
    unsigned long long wbest = 0xffffffffffffffffull;
    for (int k = w; k < ncodes; k += 2) {
        const int code = slist[k >> 3] * CH + (k & 7);
        const float4* e4 = reinterpret_cast<const float4*>(emb + (size_t)code * DIM);
        const float4* xs = reinterpret_cast<const float4*>(sx);
        float acc = 0.f;
        #pragma unroll
        for (int t = 0; t < 4; t++) {
            float4 ev = e4[l + 32 * t];
            float4 xv = xs[l + 32 * t];
            acc = fmaf(ev.x, xv.x, acc);
            acc = fmaf(ev.y, xv.y, acc);
            acc = fmaf(ev.z, xv.z, acc);
            acc = fmaf(ev.w, xv.w, acc);
        }
        #pragma unroll
        for (int off = 16; off; off >>= 1) acc += __shfl_xor_sync(0xffffffffu, acc, off);
        if (l == 0) {
            float d = __fsub_rn(__fadd_rn(xn, g_enorm[code]), 2.0f * acc);
            // d > 0 (distances ~512): float bits are order-preserving
            unsigned long long key =
                ((unsigned long long)__float_as_uint(d) << 32) | (unsigned)code;
            wbest = min(wbest, key);
        }
    }
    if (l == 0) swkey[w] = wbest;
    __syncthreads();

    if (tid == 0) {
        unsigned long long best = min(swkey[0], swkey[1]);
        int bi = (int)(best & 0xffffffffu);
        sbesti = bi;
        out[Q_ELEMS + 2 + row] = (float)bi;
        atomicMax(&g_maxidx, bi);
    }
    __syncthreads();
    const int idx = sbesti;

    // fused gather + straight-through + rowsq (2 x float4 per thread)
    float ss = 0.f;
    #pragma unroll
    for (int p = 0; p < 2; p++) {
        const int j = tid + p * 64;
        float4 qv = reinterpret_cast<const float4*>(emb + (size_t)idx * DIM)[j];
        float4 xv = reinterpret_cast<const float4*>(sx)[j];
        float4 ov;
        float d0 = __fsub_rn(qv.x, xv.x); ov.x = __fadd_rn(xv.x, d0);
        float d1 = __fsub_rn(qv.y, xv.y); ov.y = __fadd_rn(xv.y, d1);
        float d2 = __fsub_rn(qv.z, xv.z); ov.z = __fadd_rn(xv.z, d2);
        float d3 = __fsub_rn(qv.w, xv.w); ov.w = __fadd_rn(xv.w, d3);
        reinterpret_cast<float4*>(out + (size_t)row * DIM)[j] = ov;
        ss += (d0 * d0 + d1 * d1) + (d2 * d2 + d3 * d3);
    }
    #pragma unroll
    for (int off = 16; off; off >>= 1) ss += __shfl_xor_sync(0xffffffffu, ss, off);
    if (l == 0) sred[w] = ss;
    __syncthreads();
    if (tid == 0)
        g_rowsq[row] = sred[0] + sred[1];
}

// stage 1: 64 blocks x 256 threads, each reduces a fixed 256-row slice (deterministic)
__global__ void scalars_partial_kernel() {
    __shared__ float red[8];
    const int tid = threadIdx.x, w = tid >> 5, l = tid & 31;
    float s = g_rowsq[blockIdx.x * 256 + tid];
    #pragma unroll
    for (int off = 16; off; off >>= 1) s += __shfl_xor_sync(0xffffffffu, s, off);
    if (l == 0) red[w] = s;
    __syncthreads();
    if (tid == 0) {
        float t = 0.f;
        #pragma unroll
        for (int ww = 0; ww < 8; ww++) t += red[ww];
        g_part[blockIdx.x] = t;
    }
}

// stage 2: one warp finishes, fixed order
__global__ void scalars_final_kernel(float* __restrict__ out) {
    const int l = threadIdx.x;
    float s = g_part[l] + g_part[l + 32];
    #pragma unroll
    for (int off = 16; off; off >>= 1) s += __shfl_xor_sync(0xffffffffu, s, off);
    if (l == 0) {
        float mean = s / (float)Q_ELEMS;
        out[Q_ELEMS] = 1.25f * mean;
        float L = (float)(g_maxidx + 1);
        float avg = 1.0f / L;
        out[Q_ELEMS + 1] = expf(-avg * logf(avg + 1e-10f));
    }
}

extern "C" void kernel_launch(void* const* d_in, const int* in_sizes, int n_in,
                              void* d_out, int out_size) {
    const float* x   = (const float*)d_in[0];
    const float* emb = (const float*)d_in[1];
    float* out = (float*)d_out;

    cudaFuncSetAttribute(vq_gemm_kernel, cudaFuncAttributeMaxDynamicSharedMemorySize, SM_TOTAL);

    convert_kernel<<<(N_ROWS + N_CODES) / 8, 256>>>(x, emb);
    vq_gemm_kernel<<<dim3(N_ROWS / BM, N_CODES / BN), 256, SM_TOTAL>>>();
    select_kernel<<<N_ROWS, 64>>>(x, emb, out);
    scalars_partial_kernel<<<NPART, 256>>>();
    scalars_final_kernel<<<1, 32>>>(out);
}

// round 16
// speedup vs baseline: 1.1550x; 1.1550x over previous
#include <cuda_runtime.h>
#include <cuda_fp16.h>
#include <cstdint>

// ---------------- problem constants ----------------
#define N_ROWS   16384
#define N_CODES  8192
#define DIM      512
#define Q_ELEMS  (N_ROWS * DIM)

// ---------------- GEMM tiling (fp16 in, fp16 accum) ----------------
#define BM 128
#define BN 128
#define KC 64                 // K elems per stage = 128 B per row
#define NSTAGES (DIM / KC)    // 8
#define CH 8                  // codes per argmin chunk
#define NCH (N_CODES / CH)    // 1024 chunk-mins per row
#define EPS 4.0e-4f
#define MAXCAND 64            // max candidate chunks per row

// dynamic smem: 3 stages x (A 16KB + B 16KB) = 98304; enorm after -> 2 CTAs/SM
#define STG_BYTES 32768
#define SM_BOFF   16384
#define SM_ENORM  98304
#define SM_TOTAL  (98304 + 512)

#define NPART 64              // scalar reduction partials

// ---------------- scratch (device globals; no allocation allowed) ----------------
__device__ __align__(256) __half g_hx[(size_t)N_ROWS * DIM];
__device__ __align__(256) __half g_he[(size_t)N_CODES * DIM];
__device__ float  g_xnorm[N_ROWS];
__device__ float  g_enorm[N_CODES];
__device__ __align__(16) __half g_cmin[(size_t)N_ROWS * NCH];   // d~ chunk mins, fp16
__device__ float  g_rowsq[N_ROWS];
__device__ float  g_part[NPART];
__device__ int    g_maxidx;

// ---------------- PTX helpers ----------------
__device__ __forceinline__ uint32_t smem_u32(const void* p) {
    uint32_t a;
    asm("{ .reg .u64 t; cvta.to.shared.u64 t, %1; cvt.u32.u64 %0, t; }"
        : "=r"(a) : "l"(p));
    return a;
}
__device__ __forceinline__ void cp16(uint32_t dst, const void* src) {
    asm volatile("cp.async.cg.shared.global [%0], [%1], 16;" :: "r"(dst), "l"(src) : "memory");
}
__device__ __forceinline__ void cp4(uint32_t dst, const void* src) {
    asm volatile("cp.async.ca.shared.global [%0], [%1], 4;" :: "r"(dst), "l"(src) : "memory");
}
#define CP_COMMIT() asm volatile("cp.async.commit_group;" ::: "memory")
#define CP_WAIT(n)  asm volatile("cp.async.wait_group %0;" :: "n"(n) : "memory")

#define SWZ(b) ((b) ^ (((b) >> 3) & 0x70))

__device__ __forceinline__ void ldsm4(uint32_t* r, uint32_t addr) {
    asm volatile("ldmatrix.sync.aligned.m8n8.x4.shared.b16 {%0,%1,%2,%3}, [%4];"
                 : "=r"(r[0]), "=r"(r[1]), "=r"(r[2]), "=r"(r[3]) : "r"(addr));
}
// fp16 in, fp16 accum: C/D are 2 b32 regs (4 halves)
__device__ __forceinline__ void mma16816_h(uint32_t* c, const uint32_t* a, const uint32_t* b) {
    asm volatile(
        "mma.sync.aligned.m16n8k16.row.col.f16.f16.f16.f16 "
        "{%0,%1}, {%2,%3,%4,%5}, {%6,%7}, {%0,%1};"
        : "+r"(c[0]), "+r"(c[1])
        : "r"(a[0]), "r"(a[1]), "r"(a[2]), "r"(a[3]), "r"(b[0]), "r"(b[1]));
}

// ---------------- kernels ----------------

// one warp per row: fp32 norm + fp16 convert (block 0 also resets g_maxidx)
__global__ void convert_kernel(const float* __restrict__ x, const float* __restrict__ emb) {
    if (blockIdx.x == 0 && threadIdx.x == 0) g_maxidx = 0;
    int warp = (blockIdx.x * blockDim.x + threadIdx.x) >> 5;
    int lane = threadIdx.x & 31;
    const float* src; __half* dst; float* nrm; int row;
    if (warp < N_ROWS) { src = x; dst = g_hx; nrm = g_xnorm; row = warp; }
    else               { src = emb; dst = g_he; nrm = g_enorm; row = warp - N_ROWS; }
    const float4* p = reinterpret_cast<const float4*>(src + (size_t)row * DIM);
    uint2* o = reinterpret_cast<uint2*>(dst + (size_t)row * DIM);
    float s = 0.f;
    #pragma unroll
    for (int c = lane; c < DIM / 4; c += 32) {
        float4 v = p[c];
        s += v.x * v.x + v.y * v.y + v.z * v.z + v.w * v.w;
        __half2 lo = __floats2half2_rn(v.x, v.y);
        __half2 hi = __floats2half2_rn(v.z, v.w);
        uint2 u;
        u.x = *reinterpret_cast<unsigned*>(&lo);
        u.y = *reinterpret_cast<unsigned*>(&hi);
        o[c] = u;
    }
    #pragma unroll
    for (int off = 16; off; off >>= 1) s += __shfl_xor_sync(0xffffffffu, s, off);
    if (lane == 0) nrm[row] = s;
}

// fp16 HMMA GEMM: 128x128xK512 per CTA, 256 thr, 3-stage cp.async, ONE sync/stage.
// Epilogue: d~ = enorm - 2*dot, per-row min over 8-code chunks -> g_cmin (fp16).
__global__ void __launch_bounds__(256, 2) vq_gemm_kernel() {
    extern __shared__ __align__(1024) char smem[];
    const int tid = threadIdx.x;
    const int w = tid >> 5, l = tid & 31;
    const int rowBase = blockIdx.x * BM;
    const int cb = blockIdx.y * BN;
    const uint32_t sb = smem_u32(smem);
    float* senorm = reinterpret_cast<float*>(smem + SM_ENORM);

    // enorm tile via cp.async, joins stage-0 commit group (needed only in epilogue)
    if (tid < BN) cp4(sb + SM_ENORM + tid * 4u, g_enorm + cb + tid);

    // warp layout: 2 (M) x 4 (N); warp tile 64 x 32
    const int m0 = (w >> 2) * 64;
    const int n0 = (w & 3) * 32;
    const int aRowLane = l & 15;
    const int aChunkHi = l >> 4;
    const int bRowLane = ((l >> 4) & 1) * 8 + (l & 7);
    const int bChunkHi = (l >> 3) & 1;

    uint32_t c[4][4][2];
    #pragma unroll
    for (int mt = 0; mt < 4; mt++)
        #pragma unroll
        for (int nt = 0; nt < 4; nt++) { c[mt][nt][0] = 0u; c[mt][nt][1] = 0u; }

    auto load_stage = [&](int kc, int s) {
        const int kb = kc * KC;
        const uint32_t stg = sb + (uint32_t)s * STG_BYTES;
        #pragma unroll
        for (int q = 0; q < 4; q++) {
            int t = tid + q * 256;
            int r = t >> 3, ch = t & 7;
            cp16(stg + SWZ((uint32_t)(r * 128 + ch * 16)),
                 g_hx + (size_t)(rowBase + r) * DIM + kb + ch * 8);
        }
        #pragma unroll
        for (int q = 0; q < 4; q++) {
            int t = tid + q * 256;
            int r = t >> 3, ch = t & 7;
            cp16(stg + SM_BOFF + SWZ((uint32_t)(r * 128 + ch * 16)),
                 g_he + (size_t)(cb + r) * DIM + kb + ch * 8);
        }
        CP_COMMIT();
    };

    load_stage(0, 0);
    load_stage(1, 1);

    #pragma unroll
    for (int i = 0; i < NSTAGES; i++) {
        if (i < NSTAGES - 1) CP_WAIT(1); else CP_WAIT(0);
        __syncthreads();
        if (i + 2 < NSTAGES) load_stage(i + 2, (i + 2) % 3);
        const uint32_t aStg = sb + (uint32_t)(i % 3) * STG_BYTES;
        const uint32_t bStg = aStg + SM_BOFF;
        #pragma unroll
        for (int ks = 0; ks < 4; ks++) {
            uint32_t a[4][4], b[4][2];
            #pragma unroll
            for (int mt = 0; mt < 4; mt++) {
                uint32_t off = (uint32_t)((m0 + mt * 16 + aRowLane) * 128
                                          + (ks * 2 + aChunkHi) * 16);
                ldsm4(a[mt], aStg + SWZ(off));
            }
            #pragma unroll
            for (int nt2 = 0; nt2 < 2; nt2++) {
                uint32_t r4[4];
                uint32_t off = (uint32_t)((n0 + nt2 * 16 + bRowLane) * 128
                                          + (ks * 2 + bChunkHi) * 16);
                ldsm4(r4, bStg + SWZ(off));
                b[nt2 * 2][0] = r4[0]; b[nt2 * 2][1] = r4[1];
                b[nt2 * 2 + 1][0] = r4[2]; b[nt2 * 2 + 1][1] = r4[3];
            }
            #pragma unroll
            for (int mt = 0; mt < 4; mt++)
                #pragma unroll
                for (int nt = 0; nt < 4; nt++)
                    mma16816_h(c[mt][nt], a[mt], b[nt]);
        }
    }

    // ---- epilogue: chunk (8-code) mins -> smem staging -> coalesced fp16 gmem
    __syncthreads();
    float* sbuf = reinterpret_cast<float*>(smem);   // [128][20]

    #pragma unroll
    for (int mt = 0; mt < 4; mt++) {
        #pragma unroll
        for (int nt = 0; nt < 4; nt++) {
            const int colBase = n0 + nt * 8 + (l & 3) * 2;
            float en0 = senorm[colBase], en1 = senorm[colBase + 1];
            __half2 h0 = *reinterpret_cast<__half2*>(&c[mt][nt][0]);  // row r
            __half2 h1 = *reinterpret_cast<__half2*>(&c[mt][nt][1]);  // row r+8
            float v0 = fminf(en0 - 2.0f * __low2float(h0), en1 - 2.0f * __high2float(h0));
            float v1 = fminf(en0 - 2.0f * __low2float(h1), en1 - 2.0f * __high2float(h1));
            #pragma unroll
            for (int off = 1; off <= 2; off <<= 1) {
                v0 = fminf(v0, __shfl_xor_sync(0xffffffffu, v0, off));
                v1 = fminf(v1, __shfl_xor_sync(0xffffffffu, v1, off));
            }
            if ((l & 3) == 0) {
                int rloc = m0 + mt * 16 + (l >> 2);
                int chLoc = (w & 3) * 4 + nt;
                sbuf[rloc * 20 + chLoc] = v0;
                sbuf[(rloc + 8) * 20 + chLoc] = v1;
            }
        }
    }
    __syncthreads();
    {
        int row = tid >> 1, half = tid & 1;
        const float* s = &sbuf[row * 20 + half * 8];
        __half2 p0 = __floats2half2_rn(s[0], s[1]);
        __half2 p1 = __floats2half2_rn(s[2], s[3]);
        __half2 p2 = __floats2half2_rn(s[4], s[5]);
        __half2 p3 = __floats2half2_rn(s[6], s[7]);
        uint4 o;
        o.x = *reinterpret_cast<unsigned*>(&p0);
        o.y = *reinterpret_cast<unsigned*>(&p1);
        o.z = *reinterpret_cast<unsigned*>(&p2);
        o.w = *reinterpret_cast<unsigned*>(&p3);
        __half* dst = &g_cmin[(size_t)(blockIdx.x * BM + row) * NCH + blockIdx.y * 16 + half * 8];
        *reinterpret_cast<uint4*>(dst) = o;
    }
}

// block-per-row fused select, 64 threads (2 warps) for row concurrency.
// x-row prefetched via cp.async during the cmin scan; per-warp register-held
// best keys (packed u64 = exact first-index ties); fused gather/ST/rowsq.
__global__ void __launch_bounds__(64) select_kernel(const float* __restrict__ x,
                                                    const float* __restrict__ emb,
                                                    float* __restrict__ out) {
    __shared__ __align__(16) float sx[DIM];
    __shared__ float sred[2];
    __shared__ int   slist[MAXCAND];
    __shared__ int   scount;
    __shared__ unsigned long long swkey[2];
    __shared__ int   sbesti;

    const int row = blockIdx.x;
    const int tid = threadIdx.x, w = tid >> 5, l = tid & 31;
    const uint32_t sxb = smem_u32(sx);

    // prefetch x row: 2 x 16B per thread (overlaps with cmin scan below)
    cp16(sxb + tid * 16u, x + (size_t)row * DIM + tid * 4);
    cp16(sxb + (tid + 64) * 16u, x + (size_t)row * DIM + (tid + 64) * 4);
    CP_COMMIT();
    if (tid == 0) scount = 0;

    // scan: each thread holds 16 chunk-mins (2 x uint4), coalesced 2KB row
    const uint4* cm = reinterpret_cast<const uint4*>(&g_cmin[(size_t)row * NCH]);
    float fv[2][8];
    float lmin = 3.4028235e38f;
    #pragma unroll
    for (int p = 0; p < 2; p++) {
        uint4 u = cm[tid + p * 64];
        float2 f0 = __half22float2(*reinterpret_cast<__half2*>(&u.x));
        float2 f1 = __half22float2(*reinterpret_cast<__half2*>(&u.y));
        float2 f2 = __half22float2(*reinterpret_cast<__half2*>(&u.z));
        float2 f3 = __half22float2(*reinterpret_cast<__half2*>(&u.w));
        fv[p][0] = f0.x; fv[p][1] = f0.y; fv[p][2] = f1.x; fv[p][3] = f1.y;
        fv[p][4] = f2.x; fv[p][5] = f2.y; fv[p][6] = f3.x; fv[p][7] = f3.y;
        #pragma unroll
        for (int e = 0; e < 8; e++) lmin = fminf(lmin, fv[p][e]);
    }
    #pragma unroll
    for (int off = 16; off; off >>= 1) lmin = fminf(lmin, __shfl_xor_sync(0xffffffffu, lmin, off));
    if (l == 0) sred[w] = lmin;
    __syncthreads();
    const float thr = fminf(sred[0], sred[1]) + EPS;

    #pragma unroll
    for (int p = 0; p < 2; p++)
        #pragma unroll
        for (int e = 0; e < 8; e++) {
            if (fv[p][e] <= thr) {
                int q = atomicAdd(&scount, 1);
                if (q < MAXCAND) slist[q] = (tid + p * 64) * 8 + e;  // unordered OK (key-min)
            }
        }
    CP_WAIT(0);                 // x row resident in sx
    __syncthreads();
    const int count = min(scount, MAXCAND);
    const int ncodes = count * CH;
    const float xn = g_xnorm[row];

    // flat-parallel exact fp32 rescore: warp w handles codes w, w+2, ...
    unsigned long long wbest = 0xffffffffffffffffull;
    for (int k = w; k < ncodes; k += 2) {
        const int code = slist[k >> 3] * CH + (k & 7);
        const float4* e4 = reinterpret_cast<const float4*>(emb + (size_t)code * DIM);
        const float4* xs = reinterpret_cast<const float4*>(sx);
        float acc = 0.f;
        #pragma unroll
        for (int t = 0; t < 4; t++) {
            float4 ev = e4[l + 32 * t];
            float4 xv = xs[l + 32 * t];
            acc = fmaf(ev.x, xv.x, acc);
            acc = fmaf(ev.y, xv.y, acc);
            acc = fmaf(ev.z, xv.z, acc);
            acc = fmaf(ev.w, xv.w, acc);
        }
        #pragma unroll
        for (int off = 16; off; off >>= 1) acc += __shfl_xor_sync(0xffffffffu, acc, off);
        if (l == 0) {
            float d = __fsub_rn(__fadd_rn(xn, g_enorm[code]), 2.0f * acc);
            // d > 0 (distances ~512): float bits are order-preserving
            unsigned long long key =
                ((unsigned long long)__float_as_uint(d) << 32) | (unsigned)code;
            wbest = min(wbest, key);
        }
    }
    if (l == 0) swkey[w] = wbest;
    __syncthreads();

    if (tid == 0) {
        unsigned long long best = min(swkey[0], swkey[1]);
        int bi = (int)(best & 0xffffffffu);
        sbesti = bi;
        out[Q_ELEMS + 2 + row] = (float)bi;
        atomicMax(&g_maxidx, bi);
    }
    __syncthreads();
    const int idx = sbesti;

    // fused gather + straight-through + rowsq (2 x float4 per thread)
    float ss = 0.f;
    #pragma unroll
    for (int p = 0; p < 2; p++) {
        const int j = tid + p * 64;
        float4 qv = reinterpret_cast<const float4*>(emb + (size_t)idx * DIM)[j];
        float4 xv = reinterpret_cast<const float4*>(sx)[j];
        float4 ov;
        float d0 = __fsub_rn(qv.x, xv.x); ov.x = __fadd_rn(xv.x, d0);
        float d1 = __fsub_rn(qv.y, xv.y); ov.y = __fadd_rn(xv.y, d1);
        float d2 = __fsub_rn(qv.z, xv.z); ov.z = __fadd_rn(xv.z, d2);
        float d3 = __fsub_rn(qv.w, xv.w); ov.w = __fadd_rn(xv.w, d3);
        reinterpret_cast<float4*>(out + (size_t)row * DIM)[j] = ov;
        ss += (d0 * d0 + d1 * d1) + (d2 * d2 + d3 * d3);
    }
    #pragma unroll
    for (int off = 16; off; off >>= 1) ss += __shfl_xor_sync(0xffffffffu, ss, off);
    if (l == 0) sred[w] = ss;
    __syncthreads();
    if (tid == 0)
        g_rowsq[row] = sred[0] + sred[1];
}

// stage 1: 64 blocks x 256 threads, each reduces a fixed 256-row slice (deterministic)
__global__ void scalars_partial_kernel() {
    __shared__ float red[8];
    const int tid = threadIdx.x, w = tid >> 5, l = tid & 31;
    float s = g_rowsq[blockIdx.x * 256 + tid];
    #pragma unroll
    for (int off = 16; off; off >>= 1) s += __shfl_xor_sync(0xffffffffu, s, off);
    if (l == 0) red[w] = s;
    __syncthreads();
    if (tid == 0) {
        float t = 0.f;
        #pragma unroll
        for (int ww = 0; ww < 8; ww++) t += red[ww];
        g_part[blockIdx.x] = t;
    }
}

// stage 2: one warp finishes, fixed order
__global__ void scalars_final_kernel(float* __restrict__ out) {
    const int l = threadIdx.x;
    float s = g_part[l] + g_part[l + 32];
    #pragma unroll
    for (int off = 16; off; off >>= 1) s += __shfl_xor_sync(0xffffffffu, s, off);
    if (l == 0) {
        float mean = s / (float)Q_ELEMS;
        out[Q_ELEMS] = 1.25f * mean;
        float L = (float)(g_maxidx + 1);
        float avg = 1.0f / L;
        out[Q_ELEMS + 1] = expf(-avg * logf(avg + 1e-10f));
    }
}

extern "C" void kernel_launch(void* const* d_in, const int* in_sizes, int n_in,
                              void* d_out, int out_size) {
    const float* x   = (const float*)d_in[0];
    const float* emb = (const float*)d_in[1];
    float* out = (float*)d_out;

    cudaFuncSetAttribute(vq_gemm_kernel, cudaFuncAttributeMaxDynamicSharedMemorySize, SM_TOTAL);

    convert_kernel<<<(N_ROWS + N_CODES) / 16, 512>>>(x, emb);
    vq_gemm_kernel<<<dim3(N_ROWS / BM, N_CODES / BN), 256, SM_TOTAL>>>();
    select_kernel<<<N_ROWS, 64>>>(x, emb, out);
    scalars_partial_kernel<<<NPART, 256>>>();
    scalars_final_kernel<<<1, 32>>>(out);
}